// round 8
// baseline (speedup 1.0000x reference)
#include <cuda_runtime.h>
#include <cuda_fp16.h>
#include <cuda_bf16.h>

// Problem constants
#define Bn 4
#define Cn 64
#define Hn 96
#define Wn 96
#define PLANE (Hn*Wn)            // 9216
#define NPLANES (Bn*Cn)          // 256
#define NTOT (NPLANES*PLANE)     // 2359296
#define CNT_PER_CH (Bn*PLANE)    // 36864
#define BN_EPS 1e-5f
#define NPART 36                 // partial sums per channel: Bn * (3x3 blocks)

// Scratch (__device__ globals; allocation-free rule)
__device__ float g_y[NTOT];
__device__ float g_psum[Cn * NPART];
__device__ float g_psq [Cn * NPART];

// ---------------------------------------------------------------------------
// Kernel 1: fused KAN depthwise conv + race-free per-channel partial sums
// grid = (3, 3, 256 planes), block = 256 threads (32 x 8), 4 rows/thread.
// Tile element = float4 {silu, u, bitcast(coef row byte offset), 0} -> the
// tap loop is ONE LDS.128 + ONE LDS.64 + FMAs. Reg-capped for 6 blocks/SM.
// ---------------------------------------------------------------------------
__global__ __launch_bounds__(256, 6)
void kan_conv_kernel(const float* __restrict__ x,
                     const float* __restrict__ base_weight,    // (9)
                     const float* __restrict__ spline_weight,  // (9,8)
                     const float* __restrict__ spline_scaler)  // (9)
{
    __shared__ __align__(16) float4 s_t[34 * 34];   // {silu, u, mo bits, 0}
    __shared__ uint2  s_coef[12 * 9];               // half2(c0,c1), half2(c2,c3)
    __shared__ float  s_bw[9];
    __shared__ float  s_rs[8], s_rq[8];

    const int tid   = threadIdx.x;
    const int plane = blockIdx.z;
    const int ty0   = blockIdx.y * 32;
    const int tx0   = blockIdx.x * 32;

    // ---- build coefficient table (uniform cubic B-spline, closed form) ----
    if (tid < 108) {
        const int m = tid / 9, k = tid % 9;
        float c0 = 0.f, c1 = 0.f, c2 = 0.f, c3 = 0.f;
        if (m < 11) {
            const float F[4][4] = {
                {1.f, -3.f,  3.f, -1.f},   // N_{m-3}
                {4.f,  0.f, -6.f,  3.f},   // N_{m-2}
                {1.f,  3.f,  3.f, -3.f},   // N_{m-1}
                {0.f,  0.f,  0.f,  1.f}    // N_{m}
            };
            const float sc = spline_scaler[k];
            #pragma unroll
            for (int r = 0; r < 4; r++) {
                int j = m - 3 + r;
                if (j >= 0 && j < 8) {
                    float w = spline_weight[k * 8 + j] * sc;
                    c0 += w * F[r][0]; c1 += w * F[r][1];
                    c2 += w * F[r][2]; c3 += w * F[r][3];
                }
            }
        }
        const float inv6 = 1.0f / 6.0f;
        __half2 h01 = __floats2half2_rn(c0 * inv6, c1 * inv6);
        __half2 h23 = __floats2half2_rn(c2 * inv6, c3 * inv6);
        uint2 w;
        w.x = *reinterpret_cast<unsigned*>(&h01);
        w.y = *reinterpret_cast<unsigned*>(&h23);
        s_coef[m * 9 + k] = w;
    }
    if (tid < 9) s_bw[tid] = base_weight[tid];

    // ---- load + transform + decode halo tile (34x34) ----
    const float* xp = x + plane * PLANE;
    for (int i = tid; i < 34 * 34; i += 256) {
        int hy = i / 34, hx = i % 34;
        int gy = ty0 + hy - 1, gx = tx0 + hx - 1;
        float v = (gy >= 0 && gy < Hn && gx >= 0 && gx < Wn) ? xp[gy * Wn + gx] : 0.0f;
        float s  = __fdividef(v, 1.0f + __expf(-v));   // silu
        float mu = (v + 2.2f) * 2.5f;                  // (x - t0)/h
        if (!(mu >= 0.0f && mu < 11.0f)) mu = 11.0f;   // sentinel -> zero row
        int   m = (int)mu;
        float u = mu - (float)m;
        s_t[i] = make_float4(s, u, __int_as_float(m * 72), 0.0f);
    }
    __syncthreads();

    // ---- compute 32x32 outputs (4 strided rows per thread) ----
    const int tx  = tid & 31;
    const int tyb = tid >> 5;
    float lsum = 0.f, lsq = 0.f;
    const char* cbase = (const char*)s_coef;

    #pragma unroll
    for (int r = 0; r < 4; r++) {
        const int oy = tyb + r * 8;
        float acc = 0.f;
        #pragma unroll
        for (int dy = 0; dy < 3; dy++) {
            const float4* rp = &s_t[(oy + dy) * 34 + tx];
            #pragma unroll
            for (int dx = 0; dx < 3; dx++) {
                const int k = dy * 3 + dx;
                float4 t  = rp[dx];
                uint2  cw = *(const uint2*)(cbase + __float_as_int(t.z) + k * 8);
                float2 c01 = __half22float2(*reinterpret_cast<__half2*>(&cw.x));
                float2 c23 = __half22float2(*reinterpret_cast<__half2*>(&cw.y));
                float poly = fmaf(t.y, fmaf(t.y, fmaf(t.y, c23.y, c23.x), c01.y), c01.x);
                acc += poly + s_bw[k] * t.x;
            }
        }
        g_y[plane * PLANE + (ty0 + oy) * Wn + (tx0 + tx)] = acc;
        lsum += acc;
        lsq  = fmaf(acc, acc, lsq);
    }

    // ---- block reduction -> race-free partial slot ----
    #pragma unroll
    for (int o = 16; o > 0; o >>= 1) {
        lsum += __shfl_down_sync(0xffffffffu, lsum, o);
        lsq  += __shfl_down_sync(0xffffffffu, lsq,  o);
    }
    if (tx == 0) { s_rs[tyb] = lsum; s_rq[tyb] = lsq; }
    __syncthreads();
    if (tid == 0) {
        float s = 0.f, q = 0.f;
        #pragma unroll
        for (int i = 0; i < 8; i++) { s += s_rs[i]; q += s_rq[i]; }
        const int c = plane & (Cn - 1);
        const int b = plane >> 6;
        const int slot = c * NPART + b * 9 + blockIdx.y * 3 + blockIdx.x;
        g_psum[slot] = s;
        g_psq [slot] = q;
    }
}

// ---------------------------------------------------------------------------
// Kernel 2: BatchNorm (batch stats from partials) + ReLU
// grid = (3, 256 planes), block = 256; 3 float4 per thread; per-warp
// redundant butterfly stats (no smem, no __syncthreads).
// ---------------------------------------------------------------------------
__global__ __launch_bounds__(256)
void bn_relu_kernel(const float* __restrict__ gamma,
                    const float* __restrict__ beta,
                    float* __restrict__ out)
{
    const int plane = blockIdx.y;
    const int c     = plane & (Cn - 1);
    const int tid   = threadIdx.x;
    const int lane  = tid & 31;

    // start the stats chain FIRST (it is the critical path)
    float s = g_psum[c * NPART + lane % NPART];
    float q = g_psq [c * NPART + lane % NPART];

    // then issue the 3 independent data loads
    const int base = plane * (PLANE / 4) + blockIdx.x * 768 + tid;
    float4 v0 = reinterpret_cast<const float4*>(g_y)[base];
    float4 v1 = reinterpret_cast<const float4*>(g_y)[base + 256];
    float4 v2 = reinterpret_cast<const float4*>(g_y)[base + 512];

    if (lane < NPART - 32) {
        s += g_psum[c * NPART + lane + 32];
        q += g_psq [c * NPART + lane + 32];
    }
    #pragma unroll
    for (int o = 16; o > 0; o >>= 1) {
        s += __shfl_xor_sync(0xffffffffu, s, o);
        q += __shfl_xor_sync(0xffffffffu, q, o);
    }

    const float invN = 1.0f / (float)CNT_PER_CH;
    float mean = s * invN;
    float var  = q * invN - mean * mean;
    float scl  = rsqrtf(var + BN_EPS) * gamma[c];
    float sh   = fmaf(-mean, scl, beta[c]);

    float4 o0, o1, o2;
    o0.x = fmaxf(fmaf(v0.x, scl, sh), 0.0f);
    o0.y = fmaxf(fmaf(v0.y, scl, sh), 0.0f);
    o0.z = fmaxf(fmaf(v0.z, scl, sh), 0.0f);
    o0.w = fmaxf(fmaf(v0.w, scl, sh), 0.0f);
    o1.x = fmaxf(fmaf(v1.x, scl, sh), 0.0f);
    o1.y = fmaxf(fmaf(v1.y, scl, sh), 0.0f);
    o1.z = fmaxf(fmaf(v1.z, scl, sh), 0.0f);
    o1.w = fmaxf(fmaf(v1.w, scl, sh), 0.0f);
    o2.x = fmaxf(fmaf(v2.x, scl, sh), 0.0f);
    o2.y = fmaxf(fmaf(v2.y, scl, sh), 0.0f);
    o2.z = fmaxf(fmaf(v2.z, scl, sh), 0.0f);
    o2.w = fmaxf(fmaf(v2.w, scl, sh), 0.0f);
    reinterpret_cast<float4*>(out)[base]       = o0;
    reinterpret_cast<float4*>(out)[base + 256] = o1;
    reinterpret_cast<float4*>(out)[base + 512] = o2;
}

// ---------------------------------------------------------------------------
extern "C" void kernel_launch(void* const* d_in, const int* in_sizes, int n_in,
                              void* d_out, int out_size)
{
    const float* x             = (const float*)d_in[0];
    const float* base_weight   = (const float*)d_in[1];
    const float* spline_weight = (const float*)d_in[2];
    const float* spline_scaler = (const float*)d_in[3];
    const float* bn_gamma      = (const float*)d_in[4];
    const float* bn_beta       = (const float*)d_in[5];
    float* out                 = (float*)d_out;

    dim3 grid(3, 3, NPLANES);
    kan_conv_kernel<<<grid, 256>>>(x, base_weight, spline_weight, spline_scaler);

    dim3 bgrid(3, NPLANES);   // 768 blocks, 3 float4 per thread
    bn_relu_kernel<<<bgrid, 256>>>(bn_gamma, bn_beta, out);
}

// round 9
// speedup vs baseline: 1.0735x; 1.0735x over previous
#include <cuda_runtime.h>
#include <cuda_fp16.h>
#include <cuda_bf16.h>

// Problem constants
#define Bn 4
#define Cn 64
#define Hn 96
#define Wn 96
#define PLANE (Hn*Wn)            // 9216
#define NPLANES (Bn*Cn)          // 256
#define NTOT (NPLANES*PLANE)     // 2359296
#define CNT_PER_CH (Bn*PLANE)    // 36864
#define BN_EPS 1e-5f
#define NPART 36                 // partial sums per channel: Bn * (3x3 blocks)

// Scratch (__device__ globals; allocation-free rule)
__device__ float    g_y[NTOT];
__device__ float    g_psum[Cn * NPART];
__device__ float    g_psq [Cn * NPART];
__device__ float2   g_bn  [Cn];          // (scl, sh) per channel
__device__ unsigned g_cnt [Cn];          // arrival counters (self-resetting)

__device__ __forceinline__ float silu_f(float x) {
    return __fdividef(x, 1.0f + __expf(-x));
}

// ---------------------------------------------------------------------------
// Kernel 1: KAN depthwise conv with base term FOLDED INTO the spline table.
// grid = (3, 3, 256 planes), block = 256 (32 x 8), 4 strided rows/thread.
// Per tap: LDS.64 tile + LDS.64 coef + 3 FMA + 1 FADD.  Last block per
// channel also computes the BN (scl, sh) from the 36 partials.
// ---------------------------------------------------------------------------
__global__ __launch_bounds__(256)
void kan_conv_kernel(const float* __restrict__ x,
                     const float* __restrict__ base_weight,    // (9)
                     const float* __restrict__ spline_weight,  // (9,8)
                     const float* __restrict__ spline_scaler,  // (9)
                     const float* __restrict__ gamma,
                     const float* __restrict__ beta)
{
    __shared__ float2 s_t[34 * 35];        // (u | silu, coef-row byte offset)
    __shared__ uint2  s_coef[12 * 9];      // half2(c0,c1), half2(c2,c3)
    __shared__ float  s_rs[8], s_rq[8];

    const int tid   = threadIdx.x;
    const int plane = blockIdx.z;
    const int ty0   = blockIdx.y * 32;
    const int tx0   = blockIdx.x * 32;

    // ---- build coefficient table: uniform cubic B-spline (closed form)
    //      + Hermite cubic of bw[k]*silu(x) on each interval.  Sentinel row
    //      m=11 encodes the out-of-range base term: poly(u)=bw[k]*u.
    if (tid < 108) {
        const int m = tid / 9, k = tid % 9;
        const float bwk = base_weight[k];
        float c0, c1, c2, c3;
        if (m < 11) {
            c0 = c1 = c2 = c3 = 0.f;
            const float F[4][4] = {
                {1.f, -3.f,  3.f, -1.f},   // N_{m-3}
                {4.f,  0.f, -6.f,  3.f},   // N_{m-2}
                {1.f,  3.f,  3.f, -3.f},   // N_{m-1}
                {0.f,  0.f,  0.f,  1.f}    // N_{m}
            };
            const float sc = spline_scaler[k] * (1.0f / 6.0f);
            #pragma unroll
            for (int r = 0; r < 4; r++) {
                int j = m - 3 + r;
                if (j >= 0 && j < 8) {
                    float w = spline_weight[k * 8 + j] * sc;
                    c0 += w * F[r][0]; c1 += w * F[r][1];
                    c2 += w * F[r][2]; c3 += w * F[r][3];
                }
            }
            // Hermite interpolant of silu on x-interval [x0, x0+0.4], u in [0,1)
            const float x0 = -2.2f + 0.4f * (float)m;
            const float x1 = x0 + 0.4f;
            const float f0 = silu_f(x0), f1 = silu_f(x1);
            const float sg0 = 1.0f / (1.0f + __expf(-x0));
            const float sg1 = 1.0f / (1.0f + __expf(-x1));
            const float d0 = 0.4f * sg0 * (1.0f + x0 * (1.0f - sg0));
            const float d1 = 0.4f * sg1 * (1.0f + x1 * (1.0f - sg1));
            c0 += bwk * f0;
            c1 += bwk * d0;
            c2 += bwk * (3.0f * (f1 - f0) - 2.0f * d0 - d1);
            c3 += bwk * (2.0f * (f0 - f1) + d0 + d1);
        } else {
            c0 = 0.f; c1 = bwk; c2 = 0.f; c3 = 0.f;
        }
        __half2 h01 = __floats2half2_rn(c0, c1);
        __half2 h23 = __floats2half2_rn(c2, c3);
        uint2 w;
        w.x = *reinterpret_cast<unsigned*>(&h01);
        w.y = *reinterpret_cast<unsigned*>(&h23);
        s_coef[m * 9 + k] = w;
    }

    // ---- load + transform halo tile (34x34), zero-padded outside plane ----
    const float* xp = x + plane * PLANE;
    for (int i = tid; i < 34 * 34; i += 256) {
        int hy = i / 34, hx = i % 34;
        int gy = ty0 + hy - 1, gx = tx0 + hx - 1;
        float v = (gy >= 0 && gy < Hn && gx >= 0 && gx < Wn) ? xp[gy * Wn + gx] : 0.0f;
        float mu = (v + 2.2f) * 2.5f;
        float2 e;
        if (mu >= 0.0f && mu < 11.0f) {
            int m = (int)mu;
            e = make_float2(mu - (float)m, __int_as_float(m * 72));
        } else {
            e = make_float2(silu_f(v), __int_as_float(11 * 72));
        }
        s_t[hy * 35 + hx] = e;
    }
    __syncthreads();

    // ---- compute 32x32 outputs (4 strided rows per thread) ----
    const int tx  = tid & 31;
    const int tyb = tid >> 5;
    float lsum = 0.f, lsq = 0.f;
    const char* cbase = (const char*)s_coef;

    #pragma unroll
    for (int r = 0; r < 4; r++) {
        const int oy = tyb + r * 8;
        float acc = 0.f;
        #pragma unroll
        for (int dy = 0; dy < 3; dy++) {
            #pragma unroll
            for (int dx = 0; dx < 3; dx++) {
                const int k = dy * 3 + dx;
                float2 t = s_t[(oy + dy) * 35 + (tx + dx)];
                uint2  cw = *(const uint2*)(cbase + __float_as_int(t.y) + k * 8);
                float2 c01 = __half22float2(*reinterpret_cast<__half2*>(&cw.x));
                float2 c23 = __half22float2(*reinterpret_cast<__half2*>(&cw.y));
                acc += fmaf(t.x, fmaf(t.x, fmaf(t.x, c23.y, c23.x), c01.y), c01.x);
            }
        }
        g_y[plane * PLANE + (ty0 + oy) * Wn + (tx0 + tx)] = acc;
        lsum += acc;
        lsq  = fmaf(acc, acc, lsq);
    }

    // ---- block reduction -> race-free partial slot ----
    #pragma unroll
    for (int o = 16; o > 0; o >>= 1) {
        lsum += __shfl_down_sync(0xffffffffu, lsum, o);
        lsq  += __shfl_down_sync(0xffffffffu, lsq,  o);
    }
    if (tx == 0) { s_rs[tyb] = lsum; s_rq[tyb] = lsq; }
    __syncthreads();
    if (tid == 0) {
        float s = 0.f, q = 0.f;
        #pragma unroll
        for (int i = 0; i < 8; i++) { s += s_rs[i]; q += s_rq[i]; }
        const int c = plane & (Cn - 1);
        const int b = plane >> 6;
        g_psum[c * NPART + b * 9 + blockIdx.y * 3 + blockIdx.x] = s;
        g_psq [c * NPART + b * 9 + blockIdx.y * 3 + blockIdx.x] = q;
        __threadfence();
        unsigned old = atomicAdd(&g_cnt[c], 1u);
        if (old == NPART - 1) {
            // last arrival for this channel: reduce partials, publish (scl, sh)
            atomicExch(&g_cnt[c], 0u);            // reset for next replay
            float ts = 0.f, tq = 0.f;
            #pragma unroll 4
            for (int j = 0; j < NPART; j++) {
                ts += __ldcg(&g_psum[c * NPART + j]);
                tq += __ldcg(&g_psq [c * NPART + j]);
            }
            const float invN = 1.0f / (float)CNT_PER_CH;
            float mean = ts * invN;
            float var  = tq * invN - mean * mean;
            float scl  = rsqrtf(var + BN_EPS) * gamma[c];
            g_bn[c] = make_float2(scl, fmaf(-mean, scl, beta[c]));
        }
    }
}

// ---------------------------------------------------------------------------
// Kernel 2: BatchNorm + ReLU from precomputed (scl, sh): one broadcast load,
// then pure streaming.  grid = (3, 256 planes), 3 float4 per thread.
// ---------------------------------------------------------------------------
__global__ __launch_bounds__(256)
void bn_relu_kernel(float* __restrict__ out)
{
    const int plane = blockIdx.y;
    const int c     = plane & (Cn - 1);
    const int tid   = threadIdx.x;

    const float2 bn = __ldcg(&g_bn[c]);   // broadcast, single dependent load

    const int base = plane * (PLANE / 4) + blockIdx.x * 768 + tid;
    float4 v0 = reinterpret_cast<const float4*>(g_y)[base];
    float4 v1 = reinterpret_cast<const float4*>(g_y)[base + 256];
    float4 v2 = reinterpret_cast<const float4*>(g_y)[base + 512];

    const float scl = bn.x, sh = bn.y;
    float4 o0, o1, o2;
    o0.x = fmaxf(fmaf(v0.x, scl, sh), 0.0f);
    o0.y = fmaxf(fmaf(v0.y, scl, sh), 0.0f);
    o0.z = fmaxf(fmaf(v0.z, scl, sh), 0.0f);
    o0.w = fmaxf(fmaf(v0.w, scl, sh), 0.0f);
    o1.x = fmaxf(fmaf(v1.x, scl, sh), 0.0f);
    o1.y = fmaxf(fmaf(v1.y, scl, sh), 0.0f);
    o1.z = fmaxf(fmaf(v1.z, scl, sh), 0.0f);
    o1.w = fmaxf(fmaf(v1.w, scl, sh), 0.0f);
    o2.x = fmaxf(fmaf(v2.x, scl, sh), 0.0f);
    o2.y = fmaxf(fmaf(v2.y, scl, sh), 0.0f);
    o2.z = fmaxf(fmaf(v2.z, scl, sh), 0.0f);
    o2.w = fmaxf(fmaf(v2.w, scl, sh), 0.0f);
    reinterpret_cast<float4*>(out)[base]       = o0;
    reinterpret_cast<float4*>(out)[base + 256] = o1;
    reinterpret_cast<float4*>(out)[base + 512] = o2;
}

// ---------------------------------------------------------------------------
extern "C" void kernel_launch(void* const* d_in, const int* in_sizes, int n_in,
                              void* d_out, int out_size)
{
    const float* x             = (const float*)d_in[0];
    const float* base_weight   = (const float*)d_in[1];
    const float* spline_weight = (const float*)d_in[2];
    const float* spline_scaler = (const float*)d_in[3];
    const float* bn_gamma      = (const float*)d_in[4];
    const float* bn_beta       = (const float*)d_in[5];
    float* out                 = (float*)d_out;

    dim3 grid(3, 3, NPLANES);
    kan_conv_kernel<<<grid, 256>>>(x, base_weight, spline_weight, spline_scaler,
                                   bn_gamma, bn_beta);

    dim3 bgrid(3, NPLANES);   // 768 blocks, 3 float4 per thread
    bn_relu_kernel<<<bgrid, 256>>>(out);
}